// round 2
// baseline (speedup 1.0000x reference)
#include <cuda_runtime.h>

#define Dd 128
#define NMAX 50000

// Scratch (static device globals -- no allocation allowed)
__device__ float g_u[NMAX * Dd];     // (x@W) * dinv[row], read-only during scatter
__device__ float g_agg[NMAX * Dd];   // accumulator, init = u (self loop), scatter adds u[src]
__device__ float g_h[NMAX * Dd];     // layer-0 activations
__device__ float g_dinv[NMAX];       // degree -> rsqrt(degree)

// ---------------------------------------------------------------------------
// degree pipeline
// ---------------------------------------------------------------------------
__global__ void k_init_deg(float* deg, int n) {
    int i = blockIdx.x * blockDim.x + threadIdx.x;
    if (i < n) deg[i] = 1.0f;  // self loop
}

__global__ void k_count(const int* __restrict__ dst, float* deg, int E, int n) {
    int e = blockIdx.x * blockDim.x + threadIdx.x;
    if (e < E) {
        int d = dst[e];
        if (d >= 0 && d < n) atomicAdd(&deg[d], 1.0f);
    }
}

__global__ void k_rsqrt(float* deg, int n) {
    int i = blockIdx.x * blockDim.x + threadIdx.x;
    if (i < n) deg[i] = rsqrtf(deg[i]);
}

// ---------------------------------------------------------------------------
// GEMM: C[n,128] = A[n,128] @ W[128,128]
//  dinv != null : store val*dinv[row] into BOTH C and agg (pre-scatter form)
//  dinv == null : C = (val + bias) with optional relu
// block = 256 threads, tile = 64 rows x 128 cols, each thread 8x4 outputs
// ---------------------------------------------------------------------------
__global__ void __launch_bounds__(256) k_gemm128(
    const float* __restrict__ A, const float* __restrict__ W,
    const float* __restrict__ bias, float* __restrict__ C,
    float* __restrict__ agg, const float* __restrict__ dinv,
    int n, int relu)
{
    __shared__ float Ws[32 * 128];
    __shared__ float As[64 * 32];

    int tid  = threadIdx.x;
    int row0 = blockIdx.x * 64;
    int cg   = tid & 31;   // column group: cols 4*cg .. 4*cg+3
    int rg   = tid >> 5;   // warp id: rows rg*8 .. rg*8+7

    float acc[8][4];
#pragma unroll
    for (int r = 0; r < 8; r++)
#pragma unroll
        for (int c = 0; c < 4; c++) acc[r][c] = 0.0f;

    for (int kc = 0; kc < 128; kc += 32) {
        // load W chunk [32 x 128]: 1024 float4, 4 per thread
#pragma unroll
        for (int i = 0; i < 4; i++) {
            int f  = tid + i * 256;
            int kk = f >> 5;
            int j  = (f & 31) << 2;
            *(float4*)(Ws + (f << 2)) = *(const float4*)(W + (size_t)(kc + kk) * 128 + j);
        }
        // load A chunk [64 x 32]: 512 float4, 2 per thread
#pragma unroll
        for (int i = 0; i < 2; i++) {
            int f   = tid + i * 256;
            int r   = f >> 3;
            int kk  = (f & 7) << 2;
            int row = row0 + r;
            float4 v = make_float4(0.f, 0.f, 0.f, 0.f);
            if (row < n) v = *(const float4*)(A + (size_t)row * 128 + kc + kk);
            *(float4*)(As + (f << 2)) = v;
        }
        __syncthreads();

#pragma unroll
        for (int kk = 0; kk < 32; kk++) {
            float4 w4 = *(const float4*)(Ws + kk * 128 + (cg << 2));
#pragma unroll
            for (int r = 0; r < 8; r++) {
                float a = As[(rg * 8 + r) * 32 + kk];
                acc[r][0] += a * w4.x;
                acc[r][1] += a * w4.y;
                acc[r][2] += a * w4.z;
                acc[r][3] += a * w4.w;
            }
        }
        __syncthreads();
    }

    if (dinv) {
#pragma unroll
        for (int r = 0; r < 8; r++) {
            int row = row0 + rg * 8 + r;
            if (row < n) {
                float di = dinv[row];
                float4 o = make_float4(acc[r][0] * di, acc[r][1] * di,
                                       acc[r][2] * di, acc[r][3] * di);
                *(float4*)(C   + (size_t)row * 128 + (cg << 2)) = o;
                *(float4*)(agg + (size_t)row * 128 + (cg << 2)) = o;
            }
        }
    } else {
        float4 bb = make_float4(0.f, 0.f, 0.f, 0.f);
        if (bias) bb = *(const float4*)(bias + (cg << 2));
#pragma unroll
        for (int r = 0; r < 8; r++) {
            int row = row0 + rg * 8 + r;
            if (row < n) {
                float4 o = make_float4(acc[r][0] + bb.x, acc[r][1] + bb.y,
                                       acc[r][2] + bb.z, acc[r][3] + bb.w);
                if (relu) {
                    o.x = fmaxf(o.x, 0.f); o.y = fmaxf(o.y, 0.f);
                    o.z = fmaxf(o.z, 0.f); o.w = fmaxf(o.w, 0.f);
                }
                *(float4*)(C + (size_t)row * 128 + (cg << 2)) = o;
            }
        }
    }
}

// ---------------------------------------------------------------------------
// Edge scatter: agg[dst] += u[src]   (one warp per edge, 32 x float4 RED)
// ---------------------------------------------------------------------------
__global__ void k_scatter(const float* __restrict__ u,
                          const int* __restrict__ src,
                          const int* __restrict__ dst,
                          float* __restrict__ agg, int E, int n)
{
    int gidx = blockIdx.x * blockDim.x + threadIdx.x;
    int e    = gidx >> 5;
    if (e >= E) return;
    int lane = threadIdx.x & 31;
    int s = __ldg(&src[e]);
    int d = __ldg(&dst[e]);
    if ((unsigned)s >= (unsigned)n || (unsigned)d >= (unsigned)n) return;

    float4 v = *(const float4*)(u + (size_t)s * Dd + (lane << 2));
    size_t addr = __cvta_generic_to_global(agg + (size_t)d * Dd + (lane << 2));
    asm volatile("red.global.add.v4.f32 [%0], {%1,%2,%3,%4};"
                 :: "l"(addr), "f"(v.x), "f"(v.y), "f"(v.z), "f"(v.w)
                 : "memory");
}

// ---------------------------------------------------------------------------
// Epilogue: out = (agg * dinv[row] + b), optional relu. One thread per float4.
// ---------------------------------------------------------------------------
__global__ void k_epi(const float* __restrict__ agg, const float* __restrict__ dinv,
                      const float* __restrict__ b, float* __restrict__ out,
                      int n, int relu)
{
    int i = blockIdx.x * blockDim.x + threadIdx.x;  // over n*32 float4s
    if (i >= n * 32) return;
    int row = i >> 5;
    int j4  = (i & 31) << 2;
    float di  = dinv[row];
    float4 v  = ((const float4*)agg)[i];
    float4 bb = *(const float4*)(b + j4);
    v.x = v.x * di + bb.x;
    v.y = v.y * di + bb.y;
    v.z = v.z * di + bb.z;
    v.w = v.w * di + bb.w;
    if (relu) {
        v.x = fmaxf(v.x, 0.f); v.y = fmaxf(v.y, 0.f);
        v.z = fmaxf(v.z, 0.f); v.w = fmaxf(v.w, 0.f);
    }
    ((float4*)out)[i] = v;
}

// ---------------------------------------------------------------------------
extern "C" void kernel_launch(void* const* d_in, const int* in_sizes, int n_in,
                              void* d_out, int out_size)
{
    const float* x  = (const float*)d_in[0];
    const int*   ei = (const int*)d_in[1];     // int32! (JAX x64 disabled)
    const float* W0 = (const float*)d_in[2];
    const float* b0 = (const float*)d_in[3];
    const float* W1 = (const float*)d_in[4];
    const float* b1 = (const float*)d_in[5];
    const float* Wv = (const float*)d_in[6];
    const float* bv = (const float*)d_in[7];
    const float* Wt = (const float*)d_in[8];
    const float* bt = (const float*)d_in[9];

    int n = in_sizes[0] / Dd;
    int E = in_sizes[1] / 2;
    const int* srcp = ei;
    const int* dstp = ei + E;

    float* out_h = (float*)d_out;
    float* out_v = out_h + (size_t)n * Dd;
    float* out_t = out_v + (size_t)n * Dd;

    float *u, *agg, *h, *dinv;
    cudaGetSymbolAddress((void**)&u,    g_u);
    cudaGetSymbolAddress((void**)&agg,  g_agg);
    cudaGetSymbolAddress((void**)&h,    g_h);
    cudaGetSymbolAddress((void**)&dinv, g_dinv);

    int nb256  = (n + 255) / 256;
    int eb256  = (E + 255) / 256;
    int gemmB  = (n + 63) / 64;
    int scatB  = (E + 7) / 8;          // 8 edges (warps) per 256-thread block
    int epiB   = (n * 32 + 255) / 256;

    // degree -> dinv (shared by both layers)
    k_init_deg<<<nb256, 256>>>(dinv, n);
    k_count<<<eb256, 256>>>(dstp, dinv, E, n);
    k_rsqrt<<<nb256, 256>>>(dinv, n);

    // layer 0: u = (x@W0)*dinv; agg = u; agg[dst]+=u[src]; h = relu(agg*dinv + b0)
    k_gemm128<<<gemmB, 256>>>(x, W0, nullptr, u, agg, dinv, n, 0);
    k_scatter<<<scatB, 256>>>(u, srcp, dstp, agg, E, n);
    k_epi<<<epiB, 256>>>(agg, dinv, b0, h, n, 1);

    // layer 1: same, no relu, writes h into d_out
    k_gemm128<<<gemmB, 256>>>(h, W1, nullptr, u, agg, dinv, n, 0);
    k_scatter<<<scatB, 256>>>(u, srcp, dstp, agg, E, n);
    k_epi<<<epiB, 256>>>(agg, dinv, b1, out_h, n, 0);

    // heads
    k_gemm128<<<gemmB, 256>>>(out_h, Wv, bv, out_v, nullptr, nullptr, n, 1);
    k_gemm128<<<gemmB, 256>>>(out_h, Wt, bt, out_t, nullptr, nullptr, n, 1);
}

// round 4
// speedup vs baseline: 1.2128x; 1.2128x over previous
#include <cuda_runtime.h>
#include <cstdint>

#define Dd 128
#define NMAX 50000
#define PADK 132   // smem row stride (floats) -> conflict-free fragment LDS

// Scratch (static device globals -- no allocation allowed)
__device__ float g_u[NMAX * Dd];
__device__ float g_agg[NMAX * Dd];
__device__ float g_h[NMAX * Dd];
__device__ float g_dinv[NMAX];
__device__ float g_wt[4][Dd * Dd];   // transposed + tf32-rounded weights [N,K]

__device__ __forceinline__ uint32_t f2tf32(float v) {
    uint32_t r;
    asm("cvt.rna.tf32.f32 %0, %1;" : "=r"(r) : "f"(v));
    return r;
}

__device__ __forceinline__ void mma_tf32(float c[4], uint32_t a0, uint32_t a1,
                                         uint32_t a2, uint32_t a3,
                                         uint32_t b0, uint32_t b1) {
    asm volatile(
        "mma.sync.aligned.m16n8k8.row.col.f32.tf32.tf32.f32 "
        "{%0,%1,%2,%3}, {%4,%5,%6,%7}, {%8,%9}, {%0,%1,%2,%3};"
        : "+f"(c[0]), "+f"(c[1]), "+f"(c[2]), "+f"(c[3])
        : "r"(a0), "r"(a1), "r"(a2), "r"(a3), "r"(b0), "r"(b1));
}

// ---------------------------------------------------------------------------
// tf32 mma.sync GEMM: C[n,128] = A[n,128] @ Wt^T   (Wt is [N,K], tf32 bits)
//  mode 0: aux=dinv -> C = agg = val*dinv[row]
//  mode 1: aux=bias -> C = relu(val + bias)
// grid = ceil(n/128), block = 256 (8 warps x 16-row strip)
// ---------------------------------------------------------------------------
__global__ void __launch_bounds__(256) k_mma_gemm(
    const float* __restrict__ A, const float* __restrict__ Wt,
    const float* __restrict__ aux, float* __restrict__ C,
    float* __restrict__ agg, int n, int mode)
{
    extern __shared__ float sm[];
    float* As = sm;                   // [128][PADK]
    float* Ws = sm + 128 * PADK;      // [128][PADK]
    uint32_t* Asu = (uint32_t*)As;
    uint32_t* Wsu = (uint32_t*)Ws;

    int tid  = threadIdx.x;
    int wid  = tid >> 5;
    int lane = tid & 31;
    int row0 = blockIdx.x * 128;

    // stage A (tf32-rounded, zero-pad OOB) and W (already tf32 bits)
    const uint4* Wt4 = (const uint4*)Wt;
#pragma unroll
    for (int i = 0; i < 16; i++) {
        int f = tid + i * 256;
        int r = f >> 5, j = (f & 31) << 2;
        // W
        uint4 w = Wt4[f];
        *(uint4*)(Wsu + r * PADK + j) = w;
        // A
        uint4 o = make_uint4(0, 0, 0, 0);
        int grow = row0 + r;
        if (grow < n) {
            float4 a = *(const float4*)(A + (size_t)grow * 128 + j);
            o.x = f2tf32(a.x); o.y = f2tf32(a.y); o.z = f2tf32(a.z); o.w = f2tf32(a.w);
        }
        *(uint4*)(Asu + r * PADK + j) = o;
    }
    __syncthreads();

    // compute: warp strip = rows [wid*16, wid*16+16)
    float c[16][4];
#pragma unroll
    for (int nt = 0; nt < 16; nt++)
#pragma unroll
        for (int q = 0; q < 4; q++) c[nt][q] = 0.0f;

    int ar = wid * 16 + (lane >> 2);
    int kq = lane & 3;

    for (int k = 0; k < 128; k += 8) {
        uint32_t a0 = Asu[ar * PADK + k + kq];
        uint32_t a1 = Asu[(ar + 8) * PADK + k + kq];
        uint32_t a2 = Asu[ar * PADK + k + 4 + kq];
        uint32_t a3 = Asu[(ar + 8) * PADK + k + 4 + kq];
#pragma unroll
        for (int nt = 0; nt < 16; nt++) {
            int bn = nt * 8 + (lane >> 2);
            uint32_t b0 = Wsu[bn * PADK + k + kq];
            uint32_t b1 = Wsu[bn * PADK + k + 4 + kq];
            mma_tf32(c[nt], a0, a1, a2, a3, b0, b1);
        }
    }

    // epilogue: thread owns rows r0, r0+8, cols 2*(lane&3)+nt*8 (+1)
    int r0 = row0 + wid * 16 + (lane >> 2);
    int r1 = r0 + 8;
    int cc = (lane & 3) * 2;

    if (mode == 0) {
        float d0 = (r0 < n) ? aux[r0] : 0.0f;
        float d1 = (r1 < n) ? aux[r1] : 0.0f;
#pragma unroll
        for (int nt = 0; nt < 16; nt++) {
            int col = nt * 8 + cc;
            if (r0 < n) {
                float2 v = make_float2(c[nt][0] * d0, c[nt][1] * d0);
                *(float2*)(C   + (size_t)r0 * 128 + col) = v;
                *(float2*)(agg + (size_t)r0 * 128 + col) = v;
            }
            if (r1 < n) {
                float2 v = make_float2(c[nt][2] * d1, c[nt][3] * d1);
                *(float2*)(C   + (size_t)r1 * 128 + col) = v;
                *(float2*)(agg + (size_t)r1 * 128 + col) = v;
            }
        }
    } else {
#pragma unroll
        for (int nt = 0; nt < 16; nt++) {
            int col = nt * 8 + cc;
            float2 bb = *(const float2*)(aux + col);
            if (r0 < n) {
                float2 v = make_float2(fmaxf(c[nt][0] + bb.x, 0.f),
                                       fmaxf(c[nt][1] + bb.y, 0.f));
                *(float2*)(C + (size_t)r0 * 128 + col) = v;
            }
            if (r1 < n) {
                float2 v = make_float2(fmaxf(c[nt][2] + bb.x, 0.f),
                                       fmaxf(c[nt][3] + bb.y, 0.f));
                *(float2*)(C + (size_t)r1 * 128 + col) = v;
            }
        }
    }
}

// ---------------------------------------------------------------------------
// W transpose + tf32 round: Wt[n][k] = tf32(W[k][n])
// ---------------------------------------------------------------------------
__global__ void k_wt(const float* __restrict__ W, float* __restrict__ Wt) {
    int i = blockIdx.x * blockDim.x + threadIdx.x;
    if (i < Dd * Dd) {
        int k = i >> 7, nn = i & 127;
        ((uint32_t*)Wt)[nn * Dd + k] = f2tf32(W[i]);
    }
}

// ---------------------------------------------------------------------------
// degree pipeline
// ---------------------------------------------------------------------------
__global__ void k_init_deg(float* deg, int n) {
    int i = blockIdx.x * blockDim.x + threadIdx.x;
    if (i < n) deg[i] = 1.0f;
}
__global__ void k_count(const int* __restrict__ dst, float* deg, int E, int n) {
    int e = blockIdx.x * blockDim.x + threadIdx.x;
    if (e < E) {
        int d = dst[e];
        if (d >= 0 && d < n) atomicAdd(&deg[d], 1.0f);
    }
}
__global__ void k_rsqrt(float* deg, int n) {
    int i = blockIdx.x * blockDim.x + threadIdx.x;
    if (i < n) deg[i] = rsqrtf(deg[i]);
}

// ---------------------------------------------------------------------------
// Edge scatter: agg[dst] += u[src]  (warp per edge, 32 x red.v4.f32)
// ---------------------------------------------------------------------------
__global__ void k_scatter(const float* __restrict__ u,
                          const int* __restrict__ src,
                          const int* __restrict__ dst,
                          float* __restrict__ agg, int E, int n)
{
    int gidx = blockIdx.x * blockDim.x + threadIdx.x;
    int e = gidx >> 5;
    if (e >= E) return;
    int lane = threadIdx.x & 31;
    int s = __ldg(&src[e]);
    int d = __ldg(&dst[e]);
    if ((unsigned)s >= (unsigned)n || (unsigned)d >= (unsigned)n) return;

    float4 v = *(const float4*)(u + (size_t)s * Dd + (lane << 2));
    size_t addr = __cvta_generic_to_global(agg + (size_t)d * Dd + (lane << 2));
    asm volatile("red.global.add.v4.f32 [%0], {%1,%2,%3,%4};"
                 :: "l"(addr), "f"(v.x), "f"(v.y), "f"(v.z), "f"(v.w) : "memory");
}

// ---------------------------------------------------------------------------
// Epilogue: out = agg*dinv + b, optional relu
// ---------------------------------------------------------------------------
__global__ void k_epi(const float* __restrict__ agg, const float* __restrict__ dinv,
                      const float* __restrict__ b, float* __restrict__ out,
                      int n, int relu)
{
    int i = blockIdx.x * blockDim.x + threadIdx.x;
    if (i >= n * 32) return;
    int row = i >> 5;
    int j4 = (i & 31) << 2;
    float di = dinv[row];
    float4 v = ((const float4*)agg)[i];
    float4 bb = *(const float4*)(b + j4);
    v.x = v.x * di + bb.x;
    v.y = v.y * di + bb.y;
    v.z = v.z * di + bb.z;
    v.w = v.w * di + bb.w;
    if (relu) {
        v.x = fmaxf(v.x, 0.f); v.y = fmaxf(v.y, 0.f);
        v.z = fmaxf(v.z, 0.f); v.w = fmaxf(v.w, 0.f);
    }
    ((float4*)out)[i] = v;
}

// ---------------------------------------------------------------------------
extern "C" void kernel_launch(void* const* d_in, const int* in_sizes, int n_in,
                              void* d_out, int out_size)
{
    const float* x  = (const float*)d_in[0];
    const int*   ei = (const int*)d_in[1];     // int32 (JAX x64 disabled)
    const float* W0 = (const float*)d_in[2];
    const float* b0 = (const float*)d_in[3];
    const float* W1 = (const float*)d_in[4];
    const float* b1 = (const float*)d_in[5];
    const float* Wv = (const float*)d_in[6];
    const float* bv = (const float*)d_in[7];
    const float* Wt = (const float*)d_in[8];
    const float* bt = (const float*)d_in[9];

    int n = in_sizes[0] / Dd;
    int E = in_sizes[1] / 2;
    const int* srcp = ei;
    const int* dstp = ei + E;

    float* out_h = (float*)d_out;
    float* out_v = out_h + (size_t)n * Dd;
    float* out_t = out_v + (size_t)n * Dd;

    float *u, *agg, *h, *dinv, *wt;
    cudaGetSymbolAddress((void**)&u,    g_u);
    cudaGetSymbolAddress((void**)&agg,  g_agg);
    cudaGetSymbolAddress((void**)&h,    g_h);
    cudaGetSymbolAddress((void**)&dinv, g_dinv);
    cudaGetSymbolAddress((void**)&wt,   g_wt);

    float* wt0 = wt;
    float* wt1 = wt + Dd * Dd;
    float* wtv = wt + 2 * Dd * Dd;
    float* wtt = wt + 3 * Dd * Dd;

    const int SMEM_GEMM = 2 * 128 * PADK * 4;   // 135168 bytes

    static bool attr_set = false;
    if (!attr_set) {
        cudaFuncSetAttribute(k_mma_gemm, cudaFuncAttributeMaxDynamicSharedMemorySize, SMEM_GEMM);
        attr_set = true;
    }

    int nb256 = (n + 255) / 256;
    int eb256 = (E + 255) / 256;
    int gemmB = (n + 127) / 128;
    int scatB = (E + 7) / 8;
    int epiB  = (n * 32 + 255) / 256;
    int wtB   = (Dd * Dd + 255) / 256;

    // weight prep + degree pipeline
    k_wt<<<wtB, 256>>>(W0, wt0);
    k_wt<<<wtB, 256>>>(W1, wt1);
    k_wt<<<wtB, 256>>>(Wv, wtv);
    k_wt<<<wtB, 256>>>(Wt, wtt);
    k_init_deg<<<nb256, 256>>>(dinv, n);
    k_count<<<eb256, 256>>>(dstp, dinv, E, n);
    k_rsqrt<<<nb256, 256>>>(dinv, n);

    // layer 0
    k_mma_gemm<<<gemmB, 256, SMEM_GEMM>>>(x, wt0, dinv, u, agg, n, 0);
    k_scatter<<<scatB, 256>>>(u, srcp, dstp, agg, E, n);
    k_epi<<<epiB, 256>>>(agg, dinv, b0, h, n, 1);

    // layer 1 (no relu), writes h into d_out
    k_mma_gemm<<<gemmB, 256, SMEM_GEMM>>>(h, wt1, dinv, u, agg, n, 0);
    k_scatter<<<scatB, 256>>>(u, srcp, dstp, agg, E, n);
    k_epi<<<epiB, 256>>>(agg, dinv, b1, out_h, n, 0);

    // heads
    k_mma_gemm<<<gemmB, 256, SMEM_GEMM>>>(out_h, wtv, bv, out_v, nullptr, n, 1);
    k_mma_gemm<<<gemmB, 256, SMEM_GEMM>>>(out_h, wtt, bt, out_t, nullptr, n, 1);
}

// round 5
// speedup vs baseline: 2.3253x; 1.9174x over previous
#include <cuda_runtime.h>
#include <cstdint>

#define Dd 128
#define NMAX 50000
#define EMAX 1000000
#define PADW 132   // W smem row stride (floats)
#define PADA 68    // A-chunk smem row stride (floats)

// Scratch (static device globals -- no allocation allowed)
__device__ float g_u[NMAX * Dd];
__device__ float g_h[NMAX * Dd];
__device__ float g_dinv[NMAX];
__device__ float g_wt[4][Dd * Dd];   // transposed + tf32-rounded weights [N,K]
__device__ int   g_cnt[NMAX];        // in-degree (no self loop)
__device__ int   g_offs[NMAX];       // CSR offsets (exclusive scan of cnt)
__device__ int   g_cur[NMAX];        // fill cursors
__device__ int   g_csr[EMAX];        // src ids grouped by dst
__device__ int   g_bsum[256];        // scan block sums

__device__ __forceinline__ uint32_t f2tf32(float v) {
    uint32_t r;
    asm("cvt.rna.tf32.f32 %0, %1;" : "=r"(r) : "f"(v));
    return r;
}

__device__ __forceinline__ void mma_tf32(float c[4], uint32_t a0, uint32_t a1,
                                         uint32_t a2, uint32_t a3,
                                         uint32_t b0, uint32_t b1) {
    asm volatile(
        "mma.sync.aligned.m16n8k8.row.col.f32.tf32.tf32.f32 "
        "{%0,%1,%2,%3}, {%4,%5,%6,%7}, {%8,%9}, {%0,%1,%2,%3};"
        : "+f"(c[0]), "+f"(c[1]), "+f"(c[2]), "+f"(c[3])
        : "r"(a0), "r"(a1), "r"(a2), "r"(a3), "r"(b0), "r"(b1));
}

// ---------------------------------------------------------------------------
// tf32 mma.sync GEMM: C[n,128] = A[n,128] @ Wt^T   (Wt is [N,K], tf32 bits)
//  mode 0: aux=dinv -> C = val*dinv[row]
//  mode 1: aux=bias -> C = relu(val + bias)
// grid = ceil(n/128), block = 256 (8 warps x 16-row strip), 2 blocks/SM
// ---------------------------------------------------------------------------
__global__ void __launch_bounds__(256, 2) k_mma_gemm(
    const float* __restrict__ A, const float* __restrict__ Wt,
    const float* __restrict__ aux, float* __restrict__ C,
    int n, int mode)
{
    extern __shared__ float sm[];
    float* Ws = sm;                   // [128][PADW]
    float* As = sm + 128 * PADW;      // [128][PADA]
    uint32_t* Asu = (uint32_t*)As;
    uint32_t* Wsu = (uint32_t*)Ws;

    int tid  = threadIdx.x;
    int wid  = tid >> 5;
    int lane = tid & 31;
    int row0 = blockIdx.x * 128;

    // stage full W [128 N x 128 K] once (already tf32 bits)
    const uint4* Wt4 = (const uint4*)Wt;
#pragma unroll
    for (int i = 0; i < 16; i++) {
        int f = tid + i * 256;
        int r = f >> 5, j = (f & 31) << 2;
        *(uint4*)(Wsu + r * PADW + j) = Wt4[f];
    }

    float c[16][4];
#pragma unroll
    for (int nt = 0; nt < 16; nt++)
#pragma unroll
        for (int q = 0; q < 4; q++) c[nt][q] = 0.0f;

    int arow = wid * 16 + (lane >> 2);
    int kq   = lane & 3;

    for (int kc = 0; kc < 128; kc += 64) {
        // stage A chunk [128 rows x 64 K] (tf32-rounded, zero-pad OOB)
#pragma unroll
        for (int i = 0; i < 8; i++) {
            int f = tid + i * 256;
            int r = f >> 4, j = (f & 15) << 2;
            uint4 o = make_uint4(0, 0, 0, 0);
            int grow = row0 + r;
            if (grow < n) {
                float4 a = *(const float4*)(A + (size_t)grow * 128 + kc + j);
                o.x = f2tf32(a.x); o.y = f2tf32(a.y); o.z = f2tf32(a.z); o.w = f2tf32(a.w);
            }
            *(uint4*)(Asu + r * PADA + j) = o;
        }
        __syncthreads();

#pragma unroll
        for (int k = 0; k < 64; k += 8) {
            uint32_t a0 = Asu[arow * PADA + k + kq];
            uint32_t a1 = Asu[(arow + 8) * PADA + k + kq];
            uint32_t a2 = Asu[arow * PADA + k + 4 + kq];
            uint32_t a3 = Asu[(arow + 8) * PADA + k + 4 + kq];
            int kg = kc + k;
#pragma unroll
            for (int nt = 0; nt < 16; nt++) {
                int bn = nt * 8 + (lane >> 2);
                uint32_t b0 = Wsu[bn * PADW + kg + kq];
                uint32_t b1 = Wsu[bn * PADW + kg + 4 + kq];
                mma_tf32(c[nt], a0, a1, a2, a3, b0, b1);
            }
        }
        __syncthreads();
    }

    // epilogue
    int r0 = row0 + wid * 16 + (lane >> 2);
    int r1 = r0 + 8;
    int cc = (lane & 3) * 2;

    if (mode == 0) {
        float d0 = (r0 < n) ? aux[r0] : 0.0f;
        float d1 = (r1 < n) ? aux[r1] : 0.0f;
#pragma unroll
        for (int nt = 0; nt < 16; nt++) {
            int col = nt * 8 + cc;
            if (r0 < n)
                *(float2*)(C + (size_t)r0 * 128 + col) =
                    make_float2(c[nt][0] * d0, c[nt][1] * d0);
            if (r1 < n)
                *(float2*)(C + (size_t)r1 * 128 + col) =
                    make_float2(c[nt][2] * d1, c[nt][3] * d1);
        }
    } else {
#pragma unroll
        for (int nt = 0; nt < 16; nt++) {
            int col = nt * 8 + cc;
            float2 bb = *(const float2*)(aux + col);
            if (r0 < n)
                *(float2*)(C + (size_t)r0 * 128 + col) =
                    make_float2(fmaxf(c[nt][0] + bb.x, 0.f), fmaxf(c[nt][1] + bb.y, 0.f));
            if (r1 < n)
                *(float2*)(C + (size_t)r1 * 128 + col) =
                    make_float2(fmaxf(c[nt][2] + bb.x, 0.f), fmaxf(c[nt][3] + bb.y, 0.f));
        }
    }
}

// ---------------------------------------------------------------------------
// all-4 W transpose + tf32 round: Wt[n][k] = tf32(W[k][n])
// ---------------------------------------------------------------------------
__global__ void k_wt4(const float* __restrict__ W0, const float* __restrict__ W1,
                      const float* __restrict__ W2, const float* __restrict__ W3,
                      float* __restrict__ Wt) {
    int i = blockIdx.x * blockDim.x + threadIdx.x;
    if (i >= 4 * Dd * Dd) return;
    int w = i >> 14, r = i & (Dd * Dd - 1);
    const float* W = (w == 0) ? W0 : (w == 1) ? W1 : (w == 2) ? W2 : W3;
    int k = r >> 7, nn = r & 127;
    ((uint32_t*)Wt)[w * Dd * Dd + nn * Dd + k] = f2tf32(W[k * Dd + nn]);
}

// ---------------------------------------------------------------------------
// CSR build pipeline
// ---------------------------------------------------------------------------
__global__ void k_zero2(int* cnt, int* cur, int n) {
    int i = blockIdx.x * blockDim.x + threadIdx.x;
    if (i < n) { cnt[i] = 0; cur[i] = 0; }
}

__global__ void k_hist(const int* __restrict__ dst, int* cnt, int E, int n) {
    int e = blockIdx.x * blockDim.x + threadIdx.x;
    if (e < E) {
        int d = dst[e];
        if ((unsigned)d < (unsigned)n) atomicAdd(&cnt[d], 1);
    }
}

__global__ void k_scan1(const int* __restrict__ cnt, int* offs, int* bsum, int n) {
    __shared__ int s[256];
    int i = blockIdx.x * 256 + threadIdx.x;
    int v = (i < n) ? cnt[i] : 0;
    s[threadIdx.x] = v;
    __syncthreads();
#pragma unroll
    for (int d = 1; d < 256; d <<= 1) {
        int t = (threadIdx.x >= d) ? s[threadIdx.x - d] : 0;
        __syncthreads();
        s[threadIdx.x] += t;
        __syncthreads();
    }
    if (i < n) offs[i] = s[threadIdx.x] - v;
    if (threadIdx.x == 255) bsum[blockIdx.x] = s[255];
}

__global__ void k_scan2(int* bsum, int nb) {
    __shared__ int s[256];
    int v = (threadIdx.x < nb) ? bsum[threadIdx.x] : 0;
    s[threadIdx.x] = v;
    __syncthreads();
#pragma unroll
    for (int d = 1; d < 256; d <<= 1) {
        int t = (threadIdx.x >= d) ? s[threadIdx.x - d] : 0;
        __syncthreads();
        s[threadIdx.x] += t;
        __syncthreads();
    }
    if (threadIdx.x < nb) bsum[threadIdx.x] = s[threadIdx.x] - v;
}

__global__ void k_scan3(int* offs, const int* __restrict__ bsum,
                        const int* __restrict__ cnt, float* dinv, int n) {
    int i = blockIdx.x * 256 + threadIdx.x;
    if (i < n) {
        offs[i] += bsum[blockIdx.x];
        dinv[i] = rsqrtf((float)cnt[i] + 1.0f);  // +1 self loop
    }
}

__global__ void k_fill(const int* __restrict__ src, const int* __restrict__ dst,
                       const int* __restrict__ offs, int* cur, int* csr, int E, int n) {
    int e = blockIdx.x * blockDim.x + threadIdx.x;
    if (e < E) {
        int d = dst[e];
        int s = src[e];
        if ((unsigned)d < (unsigned)n && (unsigned)s < (unsigned)n) {
            int p = offs[d] + atomicAdd(&cur[d], 1);
            csr[p] = s;
        }
    }
}

// ---------------------------------------------------------------------------
// CSR gather-reduce + fused epilogue: out[i] = relu?( (u[i] + sum u[src]) * dinv[i] + b )
// warp per node, lane owns float4 column slice
// ---------------------------------------------------------------------------
__global__ void __launch_bounds__(256) k_gather(
    const float* __restrict__ u, const int* __restrict__ csr,
    const int* __restrict__ offs, const int* __restrict__ cnt,
    const float* __restrict__ dinv, const float* __restrict__ b,
    float* __restrict__ out, int n, int relu)
{
    int node = (blockIdx.x * 256 + threadIdx.x) >> 5;
    if (node >= n) return;
    int lane = threadIdx.x & 31;
    int j4 = lane << 2;

    float4 acc = *(const float4*)(u + (size_t)node * 128 + j4);  // self loop
    int beg = offs[node];
    int m = cnt[node];

    for (int base = 0; base < m; base += 32) {
        int rem = min(32, m - base);
        int s = (base + lane < m) ? __ldg(&csr[beg + base + lane]) : 0;
#pragma unroll 4
        for (int j = 0; j < rem; j++) {
            int sj = __shfl_sync(0xffffffff, s, j);
            float4 v = *(const float4*)(u + (size_t)sj * 128 + j4);
            acc.x += v.x; acc.y += v.y; acc.z += v.z; acc.w += v.w;
        }
    }

    float di = dinv[node];
    float4 bb = *(const float4*)(b + j4);
    acc.x = acc.x * di + bb.x;
    acc.y = acc.y * di + bb.y;
    acc.z = acc.z * di + bb.z;
    acc.w = acc.w * di + bb.w;
    if (relu) {
        acc.x = fmaxf(acc.x, 0.f); acc.y = fmaxf(acc.y, 0.f);
        acc.z = fmaxf(acc.z, 0.f); acc.w = fmaxf(acc.w, 0.f);
    }
    *(float4*)(out + (size_t)node * 128 + j4) = acc;
}

// ---------------------------------------------------------------------------
extern "C" void kernel_launch(void* const* d_in, const int* in_sizes, int n_in,
                              void* d_out, int out_size)
{
    const float* x  = (const float*)d_in[0];
    const int*   ei = (const int*)d_in[1];     // int32 (JAX x64 disabled)
    const float* W0 = (const float*)d_in[2];
    const float* b0 = (const float*)d_in[3];
    const float* W1 = (const float*)d_in[4];
    const float* b1 = (const float*)d_in[5];
    const float* Wv = (const float*)d_in[6];
    const float* bv = (const float*)d_in[7];
    const float* Wt = (const float*)d_in[8];
    const float* bt = (const float*)d_in[9];

    int n = in_sizes[0] / Dd;
    int E = in_sizes[1] / 2;
    if (E > EMAX) E = EMAX;
    const int* srcp = ei;
    const int* dstp = ei + E;

    float* out_h = (float*)d_out;
    float* out_v = out_h + (size_t)n * Dd;
    float* out_t = out_v + (size_t)n * Dd;

    float *u, *h, *dinv, *wt;
    int *cnt, *offs, *cur, *csr, *bsum;
    cudaGetSymbolAddress((void**)&u,    g_u);
    cudaGetSymbolAddress((void**)&h,    g_h);
    cudaGetSymbolAddress((void**)&dinv, g_dinv);
    cudaGetSymbolAddress((void**)&wt,   g_wt);
    cudaGetSymbolAddress((void**)&cnt,  g_cnt);
    cudaGetSymbolAddress((void**)&offs, g_offs);
    cudaGetSymbolAddress((void**)&cur,  g_cur);
    cudaGetSymbolAddress((void**)&csr,  g_csr);
    cudaGetSymbolAddress((void**)&bsum, g_bsum);

    float* wt0 = wt;
    float* wt1 = wt + Dd * Dd;
    float* wtv = wt + 2 * Dd * Dd;
    float* wtt = wt + 3 * Dd * Dd;

    const int SMEM_GEMM = (128 * PADW + 128 * PADA) * 4;   // 102400 bytes

    static bool attr_set = false;
    if (!attr_set) {
        cudaFuncSetAttribute(k_mma_gemm, cudaFuncAttributeMaxDynamicSharedMemorySize, SMEM_GEMM);
        attr_set = true;
    }

    int nb256  = (n + 255) / 256;
    int eb256  = (E + 255) / 256;
    int gemmB  = (n + 127) / 128;
    int gathB  = (n * 32 + 255) / 256;   // warp per node
    int wtB    = (4 * Dd * Dd + 255) / 256;

    // weight prep + CSR build (cnt doubles as degree for dinv)
    k_wt4<<<wtB, 256>>>(W0, W1, Wv, Wt, wt);
    k_zero2<<<nb256, 256>>>(cnt, cur, n);
    k_hist<<<eb256, 256>>>(dstp, cnt, E, n);
    k_scan1<<<nb256, 256>>>(cnt, offs, bsum, n);
    k_scan2<<<1, 256>>>(bsum, nb256);
    k_scan3<<<nb256, 256>>>(offs, bsum, cnt, dinv, n);
    k_fill<<<eb256, 256>>>(srcp, dstp, offs, cur, csr, E, n);

    // layer 0: u = (x@W0)*dinv; h = relu((u[self]+sum u[src])*dinv + b0)
    k_mma_gemm<<<gemmB, 256, SMEM_GEMM>>>(x, wt0, dinv, u, n, 0);
    k_gather<<<gathB, 256>>>(u, csr, offs, cnt, dinv, b0, h, n, 1);

    // layer 1 (no relu), writes into d_out
    k_mma_gemm<<<gemmB, 256, SMEM_GEMM>>>(h, wt1, dinv, u, n, 0);
    k_gather<<<gathB, 256>>>(u, csr, offs, cnt, dinv, b1, out_h, n, 0);

    // heads
    k_mma_gemm<<<gemmB, 256, SMEM_GEMM>>>(out_h, wtv, bv, out_v, n, 1);
    k_mma_gemm<<<gemmB, 256, SMEM_GEMM>>>(out_h, wtt, bt, out_t, n, 1);
}

// round 6
// speedup vs baseline: 2.3350x; 1.0041x over previous
#include <cuda_runtime.h>
#include <cstdint>

#define Dd 128
#define NMAX 50000
#define EMAX 1000000
#define PADW 136   // W smem row stride (words); %32==8 -> conflict-free v2
#define PADA 72    // A smem row stride (words); %32==8 -> conflict-free v2

// Scratch (static device globals -- no allocation allowed)
__device__ float g_u[NMAX * Dd];
__device__ float g_h[NMAX * Dd];
__device__ float g_dinv[NMAX];
__device__ float g_wt[4][Dd * Dd];   // transposed + tf32 + pair-permuted weights [N][K']
__device__ int   g_cnt[NMAX];
__device__ int   g_offs[NMAX];
__device__ int   g_cur[NMAX];
__device__ int   g_csr[EMAX];
__device__ int   g_bsum[256];

__device__ __forceinline__ uint32_t f2tf32(float v) {
    uint32_t r;
    asm("cvt.rna.tf32.f32 %0, %1;" : "=r"(r) : "f"(v));
    return r;
}

__device__ __forceinline__ void mma_tf32(float c[4], uint32_t a0, uint32_t a1,
                                         uint32_t a2, uint32_t a3,
                                         uint32_t b0, uint32_t b1) {
    asm volatile(
        "mma.sync.aligned.m16n8k8.row.col.f32.tf32.tf32.f32 "
        "{%0,%1,%2,%3}, {%4,%5,%6,%7}, {%8,%9}, {%0,%1,%2,%3};"
        : "+f"(c[0]), "+f"(c[1]), "+f"(c[2]), "+f"(c[3])
        : "r"(a0), "r"(a1), "r"(a2), "r"(a3), "r"(b0), "r"(b1));
}

// ---------------------------------------------------------------------------
// tf32 mma.sync GEMM with pair-permuted smem (all fragment LDS are v2).
// Within each 8-k group, element order is (0,4,1,5,2,6,3,7) so that the
// (k, k+4) fragment pair is one 64-bit load.
//  mode 0: aux=dinv -> C = val*dinv[row]
//  mode 1: aux=bias -> C = relu(val + bias)
// If gridDim.y==2: blockIdx.y==1 switches to (Wt2, aux2, C2) [fused heads].
// ---------------------------------------------------------------------------
__global__ void __launch_bounds__(256, 2) k_mma_gemm(
    const float* __restrict__ A, const float* __restrict__ Wt,
    const float* __restrict__ aux, float* __restrict__ C,
    const float* Wt2, const float* aux2, float* C2,
    int n, int mode)
{
    if (blockIdx.y) { Wt = Wt2; aux = aux2; C = C2; }

    extern __shared__ float sm[];
    uint32_t* Wsu = (uint32_t*)sm;                 // [128][PADW]
    uint32_t* Asu = (uint32_t*)(sm + 128 * PADW);  // [128][PADA]

    int tid  = threadIdx.x;
    int wid  = tid >> 5;
    int lane = tid & 31;
    int row0 = blockIdx.x * 128;

    // stage full W [128 N x 128 K'] (already tf32 + permuted)
    const uint4* Wt4 = (const uint4*)Wt;
#pragma unroll
    for (int i = 0; i < 16; i++) {
        int f = tid + i * 256;
        int r = f >> 5, j = (f & 31) << 2;
        *(uint4*)(Wsu + r * PADW + j) = Wt4[f];
    }

    float c[16][4];
#pragma unroll
    for (int nt = 0; nt < 16; nt++)
#pragma unroll
        for (int q = 0; q < 4; q++) c[nt][q] = 0.0f;

    int arow = wid * 16 + (lane >> 2);
    int kq2  = (lane & 3) << 1;
    int bn0  = lane >> 2;

    for (int kc = 0; kc < 128; kc += 64) {
        // stage A chunk [128 rows x 64 K] tf32-rounded + pair-permuted
#pragma unroll
        for (int i = 0; i < 4; i++) {
            int f = tid + i * 256;        // 0..1023 -> (row, 8k-group)
            int r = f >> 3, g = f & 7;
            int grow = row0 + r;
            uint4 o0 = make_uint4(0, 0, 0, 0), o1 = make_uint4(0, 0, 0, 0);
            if (grow < n) {
                const float* ap = A + (size_t)grow * 128 + kc + g * 8;
                float4 lo = *(const float4*)ap;
                float4 hi = *(const float4*)(ap + 4);
                o0.x = f2tf32(lo.x); o0.y = f2tf32(hi.x);
                o0.z = f2tf32(lo.y); o0.w = f2tf32(hi.y);
                o1.x = f2tf32(lo.z); o1.y = f2tf32(hi.z);
                o1.z = f2tf32(lo.w); o1.w = f2tf32(hi.w);
            }
            uint32_t* dst = Asu + r * PADA + g * 8;
            *(uint4*)dst = o0;
            *(uint4*)(dst + 4) = o1;
        }
        __syncthreads();

#pragma unroll
        for (int ks = 0; ks < 8; ks++) {
            int kg = ks * 8;
            uint2 aA = *(const uint2*)(Asu + arow * PADA + kg + kq2);
            uint2 aB = *(const uint2*)(Asu + (arow + 8) * PADA + kg + kq2);
            int kgW = kc + kg;
#pragma unroll
            for (int nt = 0; nt < 16; nt++) {
                uint2 b = *(const uint2*)(Wsu + (nt * 8 + bn0) * PADW + kgW + kq2);
                mma_tf32(c[nt], aA.x, aB.x, aA.y, aB.y, b.x, b.y);
            }
        }
        __syncthreads();
    }

    // epilogue
    int r0 = row0 + wid * 16 + (lane >> 2);
    int r1 = r0 + 8;
    int cc = (lane & 3) * 2;

    if (mode == 0) {
        float d0 = (r0 < n) ? aux[r0] : 0.0f;
        float d1 = (r1 < n) ? aux[r1] : 0.0f;
#pragma unroll
        for (int nt = 0; nt < 16; nt++) {
            int col = nt * 8 + cc;
            if (r0 < n)
                *(float2*)(C + (size_t)r0 * 128 + col) =
                    make_float2(c[nt][0] * d0, c[nt][1] * d0);
            if (r1 < n)
                *(float2*)(C + (size_t)r1 * 128 + col) =
                    make_float2(c[nt][2] * d1, c[nt][3] * d1);
        }
    } else {
#pragma unroll
        for (int nt = 0; nt < 16; nt++) {
            int col = nt * 8 + cc;
            float2 bb = *(const float2*)(aux + col);
            if (r0 < n)
                *(float2*)(C + (size_t)r0 * 128 + col) =
                    make_float2(fmaxf(c[nt][0] + bb.x, 0.f), fmaxf(c[nt][1] + bb.y, 0.f));
            if (r1 < n)
                *(float2*)(C + (size_t)r1 * 128 + col) =
                    make_float2(fmaxf(c[nt][2] + bb.x, 0.f), fmaxf(c[nt][3] + bb.y, 0.f));
        }
    }
}

// ---------------------------------------------------------------------------
// prep: Wt[w][n][perm(k)] = tf32(W[k][n]) for 4 weights; also zero cnt[]
// perm(k) = (k & ~7) | (2*(k&3) + ((k>>2)&1))
// ---------------------------------------------------------------------------
__global__ void k_prep(const float* __restrict__ W0, const float* __restrict__ W1,
                       const float* __restrict__ W2, const float* __restrict__ W3,
                       float* __restrict__ Wt, int* __restrict__ cnt, int n) {
    int i = blockIdx.x * blockDim.x + threadIdx.x;
    if (i < 4 * Dd * Dd) {
        int w = i >> 14, r = i & (Dd * Dd - 1);
        const float* W = (w == 0) ? W0 : (w == 1) ? W1 : (w == 2) ? W2 : W3;
        int k = r >> 7, nn = r & 127;
        int kp = (k & ~7) | (2 * (k & 3) + ((k >> 2) & 1));
        ((uint32_t*)Wt)[w * Dd * Dd + nn * Dd + kp] = f2tf32(W[k * Dd + nn]);
    }
    if (i < n) cnt[i] = 0;
}

// ---------------------------------------------------------------------------
// CSR build
// ---------------------------------------------------------------------------
__global__ void k_hist(const int* __restrict__ dst, int* cnt, int E, int n) {
    int e = blockIdx.x * blockDim.x + threadIdx.x;
    if (e < E) {
        int d = dst[e];
        if ((unsigned)d < (unsigned)n) atomicAdd(&cnt[d], 1);
    }
}

__device__ __forceinline__ int warp_iscan(int v, int lane) {
#pragma unroll
    for (int d = 1; d < 32; d <<= 1) {
        int t = __shfl_up_sync(0xffffffff, v, d);
        if (lane >= d) v += t;
    }
    return v;
}

__global__ void k_scan1(const int* __restrict__ cnt, int* offs, int* bsum, int n) {
    __shared__ int ws[8];
    int tid = threadIdx.x, lane = tid & 31, wid = tid >> 5;
    int i = blockIdx.x * 256 + tid;
    int v = (i < n) ? cnt[i] : 0;
    int s = warp_iscan(v, lane);
    if (lane == 31) ws[wid] = s;
    __syncthreads();
    if (wid == 0) {
        int t = (lane < 8) ? ws[lane] : 0;
        t = warp_iscan(t, lane);
        if (lane < 8) ws[lane] = t;
    }
    __syncthreads();
    int base = wid ? ws[wid - 1] : 0;
    if (i < n) offs[i] = base + s - v;
    if (tid == 255) bsum[blockIdx.x] = base + s;
}

__global__ void k_scan2(int* bsum, int nb) {
    __shared__ int ws[8];
    int tid = threadIdx.x, lane = tid & 31, wid = tid >> 5;
    int v = (tid < nb) ? bsum[tid] : 0;
    int s = warp_iscan(v, lane);
    if (lane == 31) ws[wid] = s;
    __syncthreads();
    if (wid == 0) {
        int t = (lane < 8) ? ws[lane] : 0;
        t = warp_iscan(t, lane);
        if (lane < 8) ws[lane] = t;
    }
    __syncthreads();
    int base = wid ? ws[wid - 1] : 0;
    if (tid < nb) bsum[tid] = base + s - v;
}

__global__ void k_scan3(int* offs, const int* __restrict__ bsum,
                        const int* __restrict__ cnt, int* cur, float* dinv, int n) {
    int i = blockIdx.x * 256 + threadIdx.x;
    if (i < n) {
        offs[i] += bsum[blockIdx.x];
        cur[i] = 0;
        dinv[i] = rsqrtf((float)cnt[i] + 1.0f);  // +1 self loop
    }
}

__global__ void k_fill(const int* __restrict__ src, const int* __restrict__ dst,
                       const int* __restrict__ offs, int* cur, int* csr, int E, int n) {
    int e = blockIdx.x * blockDim.x + threadIdx.x;
    if (e < E) {
        int d = dst[e];
        int s = src[e];
        if ((unsigned)d < (unsigned)n && (unsigned)s < (unsigned)n) {
            int p = offs[d] + atomicAdd(&cur[d], 1);
            csr[p] = s;
        }
    }
}

// ---------------------------------------------------------------------------
// CSR gather-reduce + fused epilogue: out = relu?((u[i] + sum u[src])*dinv + b)
// warp per node, lane owns float4 column slice
// ---------------------------------------------------------------------------
__global__ void __launch_bounds__(256) k_gather(
    const float* __restrict__ u, const int* __restrict__ csr,
    const int* __restrict__ offs, const int* __restrict__ cnt,
    const float* __restrict__ dinv, const float* __restrict__ b,
    float* __restrict__ out, int n, int relu)
{
    int node = (blockIdx.x * 256 + threadIdx.x) >> 5;
    if (node >= n) return;
    int lane = threadIdx.x & 31;
    int j4 = lane << 2;

    float4 acc = *(const float4*)(u + (size_t)node * 128 + j4);  // self loop
    int beg = offs[node];
    int m = cnt[node];

    for (int base = 0; base < m; base += 32) {
        int rem = min(32, m - base);
        int s = (base + lane < m) ? __ldg(&csr[beg + base + lane]) : 0;
#pragma unroll 4
        for (int j = 0; j < rem; j++) {
            int sj = __shfl_sync(0xffffffff, s, j);
            float4 v = *(const float4*)(u + (size_t)sj * 128 + j4);
            acc.x += v.x; acc.y += v.y; acc.z += v.z; acc.w += v.w;
        }
    }

    float di = dinv[node];
    float4 bb = *(const float4*)(b + j4);
    acc.x = acc.x * di + bb.x;
    acc.y = acc.y * di + bb.y;
    acc.z = acc.z * di + bb.z;
    acc.w = acc.w * di + bb.w;
    if (relu) {
        acc.x = fmaxf(acc.x, 0.f); acc.y = fmaxf(acc.y, 0.f);
        acc.z = fmaxf(acc.z, 0.f); acc.w = fmaxf(acc.w, 0.f);
    }
    *(float4*)(out + (size_t)node * 128 + j4) = acc;
}

// ---------------------------------------------------------------------------
extern "C" void kernel_launch(void* const* d_in, const int* in_sizes, int n_in,
                              void* d_out, int out_size)
{
    const float* x  = (const float*)d_in[0];
    const int*   ei = (const int*)d_in[1];     // int32 (JAX x64 disabled)
    const float* W0 = (const float*)d_in[2];
    const float* b0 = (const float*)d_in[3];
    const float* W1 = (const float*)d_in[4];
    const float* b1 = (const float*)d_in[5];
    const float* Wv = (const float*)d_in[6];
    const float* bv = (const float*)d_in[7];
    const float* Wt = (const float*)d_in[8];
    const float* bt = (const float*)d_in[9];

    int n = in_sizes[0] / Dd;
    int E = in_sizes[1] / 2;
    if (E > EMAX) E = EMAX;
    const int* srcp = ei;
    const int* dstp = ei + E;

    float* out_h = (float*)d_out;
    float* out_v = out_h + (size_t)n * Dd;
    float* out_t = out_v + (size_t)n * Dd;

    float *u, *h, *dinv, *wt;
    int *cnt, *offs, *cur, *csr, *bsum;
    cudaGetSymbolAddress((void**)&u,    g_u);
    cudaGetSymbolAddress((void**)&h,    g_h);
    cudaGetSymbolAddress((void**)&dinv, g_dinv);
    cudaGetSymbolAddress((void**)&wt,   g_wt);
    cudaGetSymbolAddress((void**)&cnt,  g_cnt);
    cudaGetSymbolAddress((void**)&offs, g_offs);
    cudaGetSymbolAddress((void**)&cur,  g_cur);
    cudaGetSymbolAddress((void**)&csr,  g_csr);
    cudaGetSymbolAddress((void**)&bsum, g_bsum);

    float* wt0 = wt;
    float* wt1 = wt + Dd * Dd;
    float* wtv = wt + 2 * Dd * Dd;
    float* wtt = wt + 3 * Dd * Dd;

    const int SMEM_GEMM = (128 * PADW + 128 * PADA) * 4;   // 106496 bytes

    static bool attr_set = false;
    if (!attr_set) {
        cudaFuncSetAttribute(k_mma_gemm, cudaFuncAttributeMaxDynamicSharedMemorySize, SMEM_GEMM);
        attr_set = true;
    }

    int nb256  = (n + 255) / 256;
    int eb256  = (E + 255) / 256;
    int gemmB  = (n + 127) / 128;
    int gathB  = (n * 32 + 255) / 256;
    int prepB  = (4 * Dd * Dd + 255) / 256;   // 256 blocks >= nb256

    // prep + CSR build
    k_prep<<<prepB, 256>>>(W0, W1, Wv, Wt, wt, cnt, n);
    k_hist<<<eb256, 256>>>(dstp, cnt, E, n);
    k_scan1<<<nb256, 256>>>(cnt, offs, bsum, n);
    k_scan2<<<1, 256>>>(bsum, nb256);
    k_scan3<<<nb256, 256>>>(offs, bsum, cnt, cur, dinv, n);
    k_fill<<<eb256, 256>>>(srcp, dstp, offs, cur, csr, E, n);

    dim3 g1(gemmB, 1), g2(gemmB, 2);

    // layer 0
    k_mma_gemm<<<g1, 256, SMEM_GEMM>>>(x, wt0, dinv, u, nullptr, nullptr, nullptr, n, 0);
    k_gather<<<gathB, 256>>>(u, csr, offs, cnt, dinv, b0, h, n, 1);

    // layer 1 (no relu), writes into d_out
    k_mma_gemm<<<g1, 256, SMEM_GEMM>>>(h, wt1, dinv, u, nullptr, nullptr, nullptr, n, 0);
    k_gather<<<gathB, 256>>>(u, csr, offs, cnt, dinv, b1, out_h, n, 0);

    // both heads in one launch (blockIdx.y selects)
    k_mma_gemm<<<g2, 256, SMEM_GEMM>>>(out_h, wtv, bv, out_v, wtt, bt, out_t, n, 1);
}